// round 12
// baseline (speedup 1.0000x reference)
#include <cuda_runtime.h>
#include <math.h>
#include <stdint.h>

// Problem constants
#define BHALF 8192            // B
#define N     16384           // 2B
#define TILE  128
#define NT    (N / TILE)      // 128 tiles
#define NTRI  (NT * (NT + 1) / 2)        // 8256 triangular tiles
#define PGRID 740                         // 148 SM x 5 resident blocks: ONE wave
#define NRED  65                          // 64 rowlog + 1 prosody reduce blocks
#define EXPDIAG 7.389056098930650f       // exp(2) = exp(sim_ii / T)
#define NEG_INV_C (-0.34657359027997264f) // -1/(2*log2(e)) = -ln2/2
#define TEMP_EPS 0.01f
#define TWO_CORR 2.000122f   // Newton constant, bias-recentered (R8 calib)
#define MAGIC2 0xFEF311C3FEF311C3ULL      // dual rcp seed (no cross-half borrow)

// Scratch (deterministic: every slot has exactly one writer)
__device__ float g_part[NT * N];          // 8 MB partial row sums (L2-resident)
__device__ float g_blocksum[64];
__device__ float g_tail;
__device__ int   g_done = 0;

// ---------------- packed f32x2 helpers (sm_100 family) ----------------
__device__ __forceinline__ unsigned long long pk2(float lo, float hi) {
    unsigned long long r;
    asm("mov.b64 %0, {%1, %2};" : "=l"(r) : "f"(lo), "f"(hi));
    return r;
}
__device__ __forceinline__ float lo2(unsigned long long v) {
    float f; asm("{ .reg .f32 t; mov.b64 {%0, t}, %1; }" : "=f"(f) : "l"(v)); return f;
}
__device__ __forceinline__ float hi2(unsigned long long v) {
    float f; asm("{ .reg .f32 t; mov.b64 {t, %0}, %1; }" : "=f"(f) : "l"(v)); return f;
}
__device__ __forceinline__ unsigned long long add2(unsigned long long a, unsigned long long b) {
    unsigned long long r;
    asm("add.rn.f32x2 %0, %1, %2;" : "=l"(r) : "l"(a), "l"(b));
    return r;
}
__device__ __forceinline__ unsigned long long mul2(unsigned long long a, unsigned long long b) {
    unsigned long long r;
    asm("mul.rn.f32x2 %0, %1, %2;" : "=l"(r) : "l"(a), "l"(b));
    return r;
}
__device__ __forceinline__ unsigned long long fma2(unsigned long long a, unsigned long long b,
                                                   unsigned long long c) {
    unsigned long long r;
    asm("fma.rn.f32x2 %0, %1, %2, %3;" : "=l"(r) : "l"(a), "l"(b), "l"(c));
    return r;
}
__device__ __forceinline__ float ex2a(float x) {
    float r;
    asm("ex2.approx.ftz.f32 %0, %1;" : "=f"(r) : "f"(x));
    return r;
}

// ---------------------------------------------------------------------------
// Kernel A: PERSISTENT symmetric tile kernel. Grid = 740 (one full wave of
// 5 blocks/SM). Each block loops tile = bid, bid+740, ... < NTRI: removes
// ~10 wave transitions and the 16%-occupied final wave.
// Body per 2 pairs (proven): LDS.64, add2, and64, fma2, sub.u64 seed, fma2,
// mul2, 2x ex2, 2x add2 -> fma 6 / alu 4 / MUFU 2, issue+MUFU co-bound.
// ---------------------------------------------------------------------------
__global__ __launch_bounds__(256, 5) void tile_kernel(
    const float* __restrict__ emb_i, const float* __restrict__ emb_j)
{
    __shared__ float ra[TILE];
    __shared__ unsigned long long rbn_pad[16][5];   // packed (-rj0,-rj1), padded
    __shared__ float redR[16][TILE + 1];            // row-reduction scratch
    __shared__ float redC[16][TILE + 1];            // col-reduction scratch

    const int t  = threadIdx.x;
    const int tx = t & 15;
    const int ty = t >> 4;

    const unsigned long long cN   = pk2(NEG_INV_C, NEG_INV_C);
    const unsigned long long two2 = pk2(TWO_CORR, TWO_CORR);

    for (int tile = blockIdx.x; tile < NTRI; tile += PGRID) {
        // ---- decode triangular (a, b) from linear tile id ----
        float disc = (float)((2 * NT + 1) * (2 * NT + 1) - 8 * tile);
        int a = (int)(((float)(2 * NT + 1) - sqrtf(disc)) * 0.5f);
        a = max(0, min(a, NT - 1));
        while (a > 0 && tile < a * NT - (a * (a - 1)) / 2) a--;
        while (tile >= (a + 1) * NT - ((a + 1) * a) / 2) a++;
        const int b = a + (tile - (a * NT - (a * (a - 1)) / 2));

        // ---- load rep values (prior-iteration reads of these arrays all
        //      completed before the previous epilogue barrier) ----
        if (t < TILE) {
            int g = a * TILE + t;
            ra[t] = (g < BHALF) ? emb_i[g] : emb_j[g - BHALF];
        } else if (t < TILE + 64) {
            int j = t - TILE;                    // covers b-tile cols 2j, 2j+1
            int gi = b * TILE + 2 * j;
            float2 v = (gi < BHALF)
                     ? ((const float2*)emb_i)[gi >> 1]
                     : ((const float2*)emb_j)[(gi - BHALF) >> 1];
            rbn_pad[j >> 2][j & 3] = pk2(-v.x, -v.y);
        }
        __syncthreads();

        unsigned long long rowP[8], colP[4];
#pragma unroll
        for (int y = 0; y < 8; y++) rowP[y] = 0ULL;
#pragma unroll
        for (int x2 = 0; x2 < 4; x2++) colP[x2] = 0ULL;

#pragma unroll
        for (int y = 0; y < 8; y++) {
            const float riv = ra[ty * 8 + y];
            const unsigned long long rip = pk2(riv, riv);
#pragma unroll
            for (int x2 = 0; x2 < 4; x2++) {
                unsigned long long rjnv = rbn_pad[tx][x2];           // LDS.64, no conflicts
                unsigned long long df = add2(rip, rjnv);              // ri - rj
                df &= 0x7FFFFFFF7FFFFFFFULL;                          // |.| per half
                unsigned long long sn = fma2(df, cN, cN);             // -(1+d)/C
                unsigned long long r = MAGIC2 - sn;                   // dual rcp seed
                unsigned long long tt = fma2(sn, r, two2);            // (2+d) - |s|r
                r = mul2(r, tt);                                      // 1 Newton, recentered
                unsigned long long e2 = pk2(ex2a(lo2(r)), ex2a(hi2(r)));
                rowP[y]  = add2(rowP[y],  e2);
                colP[x2] = add2(colP[x2], e2);
            }
        }

        // ---- fused epilogue: both scratch writes, ONE barrier, both outputs ----
#pragma unroll
        for (int y = 0; y < 8; y++)
            redR[tx][ty * 8 + y] = lo2(rowP[y]) + hi2(rowP[y]);
#pragma unroll
        for (int x2 = 0; x2 < 4; x2++) {
            redC[ty][tx * 8 + 2 * x2]     = lo2(colP[x2]);
            redC[ty][tx * 8 + 2 * x2 + 1] = hi2(colP[x2]);
        }
        __syncthreads();
        if (t < TILE) {
            float sr = 0.0f;
#pragma unroll
            for (int kk = 0; kk < 16; kk++) sr += redR[kk][t];
            g_part[b * N + a * TILE + t] = sr;
            if (a != b) {
                float sc = 0.0f;
#pragma unroll
                for (int kk = 0; kk < 16; kk++) sc += redC[kk][t];
                g_part[a * N + b * TILE + t] = sc;
            }
        }
        __syncthreads();   // protect redR/redC & smem inputs before next iter
    }
}

// ---------------------------------------------------------------------------
// Kernel B: 65 blocks x 256 threads; last-finishing block also combines.
//   blocks 0..63 : per-row denominator -> __logf -> block sum  (256 rows each)
//   block 64     : prosody softmax + positives tail (fast intrinsics)
// Final combine reads g_blocksum in FIXED index order -> deterministic
// regardless of which block finishes last. Counter self-resets (graph-safe).
// ---------------------------------------------------------------------------
__global__ __launch_bounds__(256) void reduce_kernel(
    const float* __restrict__ emb_i, const float* __restrict__ emb_j,
    const float* __restrict__ pro_i, const float* __restrict__ pro_j,
    float* __restrict__ out)
{
    __shared__ float sred[256];
    const int t = threadIdx.x;
    const int role = blockIdx.x;

    if (role < 64) {
        // ---- row-log reduction: rows [role*256, role*256+256) ----
        const int i = role * 256 + t;
        float s = 0.0f;
#pragma unroll 16
        for (int kk = 0; kk < NT; kk++) s += g_part[kk * N + i];
        sred[t] = __logf(s - EXPDIAG);        // remove diagonal term exp(2)
        __syncthreads();
        for (int off = 128; off > 0; off >>= 1) {
            if (t < off) sred[t] += sred[t + off];
            __syncthreads();
        }
        if (t == 0) g_blocksum[role] = sred[0];
    } else {
        // ---- prosody softmax + positives tail (block 64) ----
        float mx = -1.0f;
        for (int bb = t; bb < BHALF; bb += 256)
            mx = fmaxf(mx, fabsf(pro_i[bb] - pro_j[bb]));
        sred[t] = mx;
        __syncthreads();
        for (int off = 128; off > 0; off >>= 1) {
            if (t < off) sred[t] = fmaxf(sred[t], sred[t + off]);
            __syncthreads();
        }
        mx = sred[0];
        __syncthreads();

        float se = 0.0f;
        for (int bb = t; bb < BHALF; bb += 256)
            se += __expf(fabsf(pro_i[bb] - pro_j[bb]) - mx);
        sred[t] = se;
        __syncthreads();
        for (int off = 128; off > 0; off >>= 1) {
            if (t < off) sred[t] += sred[t + off];
            __syncthreads();
        }
        const float invZ = 1.0f / sred[0];
        __syncthreads();

        float lp = 0.0f;
        for (int bb = t; bb < BHALF; bb += 256) {
            float pdv = fabsf(pro_i[bb] - pro_j[bb]);
            lp += __logf(__expf(pdv - mx) * invZ + TEMP_EPS);
            lp += __logf(1.0f + fabsf(emb_i[bb] - emb_j[bb]));
        }
        sred[t] = lp;
        __syncthreads();
        for (int off = 128; off > 0; off >>= 1) {
            if (t < off) sred[t] += sred[t + off];
            __syncthreads();
        }
        if (t == 0) g_tail = sred[0];
    }

    // ---- last-finishing block combines ----
    __threadfence();
    __syncthreads();
    if (t == 0) {
        int old = atomicAdd(&g_done, 1);
        if (old == NRED - 1) {
            __threadfence();
            float L1 = 0.0f;
            volatile float* bs = g_blocksum;
#pragma unroll
            for (int kk = 0; kk < 64; kk++) L1 += bs[kk];
            out[0] = (L1 + 2.0f * (*(volatile float*)&g_tail)) / (float)N;
            g_done = 0;                        // reset for next graph replay
        }
    }
}

// ---------------------------------------------------------------------------
extern "C" void kernel_launch(void* const* d_in, const int* in_sizes, int n_in,
                              void* d_out, int out_size)
{
    const float* emb_i = (const float*)d_in[0];
    const float* emb_j = (const float*)d_in[1];
    const float* pro_i = (const float*)d_in[2];
    const float* pro_j = (const float*)d_in[3];
    float* out = (float*)d_out;

    tile_kernel<<<PGRID, 256>>>(emb_i, emb_j);
    reduce_kernel<<<NRED, 256>>>(emb_i, emb_j, pro_i, pro_j, out);
}

// round 13
// speedup vs baseline: 1.1465x; 1.1465x over previous
#include <cuda_runtime.h>
#include <math.h>
#include <stdint.h>

// Problem constants
#define BHALF 8192            // B
#define N     16384           // 2B
#define TILE  128
#define NT    (N / TILE)      // 128 tiles
#define NTRI  (NT * (NT + 1) / 2)        // 8256 triangular blocks
#define EXPDIAG 7.389056098930650f       // exp(2) = exp(sim_ii / T)
#define NEG_INV_C (-0.34657359027997264f) // -1/(2*log2(e)) = -ln2/2
#define TEMP_EPS 0.01f
#define TWO_CORR 2.000122f   // Newton constant, bias-recentered (R8 calib)
#define MAGIC2 0xFEF311C3FEF311C3ULL      // dual rcp seed (no cross-half borrow)

// Scratch (deterministic: every slot has exactly one writer)
__device__ float g_part[NT * N];          // 8 MB partial row sums (L2-resident)
__device__ float g_blocksum[32];
__device__ float g_tail;

// ---------------- packed f32x2 helpers (sm_100 family) ----------------
__device__ __forceinline__ unsigned long long pk2(float lo, float hi) {
    unsigned long long r;
    asm("mov.b64 %0, {%1, %2};" : "=l"(r) : "f"(lo), "f"(hi));
    return r;
}
__device__ __forceinline__ float lo2(unsigned long long v) {
    float f; asm("{ .reg .f32 t; mov.b64 {%0, t}, %1; }" : "=f"(f) : "l"(v)); return f;
}
__device__ __forceinline__ float hi2(unsigned long long v) {
    float f; asm("{ .reg .f32 t; mov.b64 {t, %0}, %1; }" : "=f"(f) : "l"(v)); return f;
}
__device__ __forceinline__ unsigned long long add2(unsigned long long a, unsigned long long b) {
    unsigned long long r;
    asm("add.rn.f32x2 %0, %1, %2;" : "=l"(r) : "l"(a), "l"(b));
    return r;
}
__device__ __forceinline__ unsigned long long mul2(unsigned long long a, unsigned long long b) {
    unsigned long long r;
    asm("mul.rn.f32x2 %0, %1, %2;" : "=l"(r) : "l"(a), "l"(b));
    return r;
}
__device__ __forceinline__ unsigned long long fma2(unsigned long long a, unsigned long long b,
                                                   unsigned long long c) {
    unsigned long long r;
    asm("fma.rn.f32x2 %0, %1, %2, %3;" : "=l"(r) : "l"(a), "l"(b), "l"(c));
    return r;
}
__device__ __forceinline__ float ex2a(float x) {
    float r;
    asm("ex2.approx.ftz.f32 %0, %1;" : "=f"(r) : "f"(x));
    return r;
}

// ---------------------------------------------------------------------------
// Kernel A: symmetric tile kernel — EXACT R11 version (proven 45.1us).
// Per 2 pairs: LDS.64, add2, and64, fma2, sub.u64 seed, fma2, mul2, 2x ex2,
// 2x add2 -> fma 6 / alu 4 / MUFU 2; MUFU+issue co-bound.
// 5 blocks/SM (cap 51): ri re-read per y, rj packed in padded smem.
// ---------------------------------------------------------------------------
__global__ __launch_bounds__(256, 5) void tile_kernel(
    const float* __restrict__ emb_i, const float* __restrict__ emb_j)
{
    // decode triangular (a, b) from linear block id
    const int k = blockIdx.x;
    float disc = (float)((2 * NT + 1) * (2 * NT + 1) - 8 * k);
    int a = (int)(((float)(2 * NT + 1) - sqrtf(disc)) * 0.5f);
    a = max(0, min(a, NT - 1));
    while (a > 0 && k < a * NT - (a * (a - 1)) / 2) a--;
    while (k >= (a + 1) * NT - ((a + 1) * a) / 2) a++;
    const int b = a + (k - (a * NT - (a * (a - 1)) / 2));

    __shared__ float ra[TILE];
    __shared__ unsigned long long rbn_pad[16][5];   // packed (-rj0,-rj1), padded
    __shared__ float redR[16][TILE + 1];            // row-reduction scratch
    __shared__ float redC[16][TILE + 1];            // col-reduction scratch

    const int t = threadIdx.x;

    // ---- load rep values ----
    if (t < TILE) {
        int g = a * TILE + t;
        ra[t] = (g < BHALF) ? emb_i[g] : emb_j[g - BHALF];
    } else if (t < TILE + 64) {
        int j = t - TILE;                    // covers b-tile cols 2j, 2j+1
        int gi = b * TILE + 2 * j;
        float2 v = (gi < BHALF)
                 ? ((const float2*)emb_i)[gi >> 1]
                 : ((const float2*)emb_j)[(gi - BHALF) >> 1];
        rbn_pad[j >> 2][j & 3] = pk2(-v.x, -v.y);
    }
    __syncthreads();

    const int tx = t & 15;
    const int ty = t >> 4;

    const unsigned long long cN   = pk2(NEG_INV_C, NEG_INV_C);
    const unsigned long long two2 = pk2(TWO_CORR, TWO_CORR);

    unsigned long long rowP[8], colP[4];
#pragma unroll
    for (int y = 0; y < 8; y++) rowP[y] = 0ULL;
#pragma unroll
    for (int x2 = 0; x2 < 4; x2++) colP[x2] = 0ULL;

#pragma unroll
    for (int y = 0; y < 8; y++) {
        const float riv = ra[ty * 8 + y];
        const unsigned long long rip = pk2(riv, riv);
#pragma unroll
        for (int x2 = 0; x2 < 4; x2++) {
            unsigned long long rjnv = rbn_pad[tx][x2];               // LDS.64, no conflicts
            unsigned long long df = add2(rip, rjnv);                  // ri - rj
            df &= 0x7FFFFFFF7FFFFFFFULL;                              // |.| per half
            unsigned long long sn = fma2(df, cN, cN);                 // -(1+d)/C
            unsigned long long r = MAGIC2 - sn;                       // dual rcp seed
            unsigned long long tt = fma2(sn, r, two2);                // (2+d) - |s|r
            r = mul2(r, tt);                                          // 1 Newton, recentered
            unsigned long long e2 = pk2(ex2a(lo2(r)), ex2a(hi2(r)));
            rowP[y]  = add2(rowP[y],  e2);
            colP[x2] = add2(colP[x2], e2);
        }
    }

    // ---- fused epilogue: both scratch writes, ONE barrier, both outputs ----
#pragma unroll
    for (int y = 0; y < 8; y++)
        redR[tx][ty * 8 + y] = lo2(rowP[y]) + hi2(rowP[y]);
#pragma unroll
    for (int x2 = 0; x2 < 4; x2++) {
        redC[ty][tx * 8 + 2 * x2]     = lo2(colP[x2]);
        redC[ty][tx * 8 + 2 * x2 + 1] = hi2(colP[x2]);
    }
    __syncthreads();
    if (t < TILE) {
        float sr = 0.0f;
#pragma unroll
        for (int kk = 0; kk < 16; kk++) sr += redR[kk][t];
        g_part[b * N + a * TILE + t] = sr;
        if (a != b) {
            float sc = 0.0f;
#pragma unroll
            for (int kk = 0; kk < 16; kk++) sc += redC[kk][t];
            g_part[a * N + b * TILE + t] = sc;
        }
    }
}

// ---------------------------------------------------------------------------
// Kernel B: 33 blocks x 512 threads.
//   blocks 0..31 : per-row denominator -> __logf -> block sum (512 rows each)
//   block 32     : prosody softmax + positives tail, 512-thread passes
//                  (16 independent L2-latency-covered iterations per pass)
// ---------------------------------------------------------------------------
__global__ __launch_bounds__(512) void reduce_kernel(
    const float* __restrict__ emb_i, const float* __restrict__ emb_j,
    const float* __restrict__ pro_i, const float* __restrict__ pro_j)
{
    __shared__ float sred[512];
    const int t = threadIdx.x;
    const int role = blockIdx.x;

    if (role < 32) {
        // ---- row-log reduction: rows [role*512, role*512+512) ----
        const int i = role * 512 + t;
        float s = 0.0f;
#pragma unroll 16
        for (int kk = 0; kk < NT; kk++) s += g_part[kk * N + i];   // coalesced 2KB rows
        sred[t] = __logf(s - EXPDIAG);        // remove diagonal term exp(2)
        __syncthreads();
        for (int off = 256; off > 0; off >>= 1) {
            if (t < off) sred[t] += sred[t + off];
            __syncthreads();
        }
        if (t == 0) g_blocksum[role] = sred[0];
        return;
    }

    // ---- prosody softmax + positives tail (block 32, 512 threads) ----
    float mx = -1.0f;
#pragma unroll
    for (int bb = t; bb < BHALF; bb += 512)
        mx = fmaxf(mx, fabsf(pro_i[bb] - pro_j[bb]));
    sred[t] = mx;
    __syncthreads();
    for (int off = 256; off > 0; off >>= 1) {
        if (t < off) sred[t] = fmaxf(sred[t], sred[t + off]);
        __syncthreads();
    }
    mx = sred[0];
    __syncthreads();

    float se = 0.0f;
#pragma unroll
    for (int bb = t; bb < BHALF; bb += 512)
        se += __expf(fabsf(pro_i[bb] - pro_j[bb]) - mx);
    sred[t] = se;
    __syncthreads();
    for (int off = 256; off > 0; off >>= 1) {
        if (t < off) sred[t] += sred[t + off];
        __syncthreads();
    }
    const float invZ = 1.0f / sred[0];
    __syncthreads();

    float lp = 0.0f;
#pragma unroll
    for (int bb = t; bb < BHALF; bb += 512) {
        float pdv = fabsf(pro_i[bb] - pro_j[bb]);
        lp += __logf(__expf(pdv - mx) * invZ + TEMP_EPS);
        lp += __logf(1.0f + fabsf(emb_i[bb] - emb_j[bb]));
    }
    sred[t] = lp;
    __syncthreads();
    for (int off = 256; off > 0; off >>= 1) {
        if (t < off) sred[t] += sred[t + off];
        __syncthreads();
    }
    if (t == 0) g_tail = sred[0];
}

// ---------------------------------------------------------------------------
// Kernel C: final combine. 1 block, 32 threads.
// loss = (1/n) [ sum_i log(denom_i) + 2 * tail ]
// ---------------------------------------------------------------------------
__global__ __launch_bounds__(32) void combine_kernel(float* __restrict__ out)
{
    const int t = threadIdx.x;
    float v = g_blocksum[t];
#pragma unroll
    for (int off = 16; off > 0; off >>= 1)
        v += __shfl_down_sync(0xFFFFFFFFu, v, off);
    if (t == 0) out[0] = (v + 2.0f * g_tail) / (float)N;
}

// ---------------------------------------------------------------------------
extern "C" void kernel_launch(void* const* d_in, const int* in_sizes, int n_in,
                              void* d_out, int out_size)
{
    const float* emb_i = (const float*)d_in[0];
    const float* emb_j = (const float*)d_in[1];
    const float* pro_i = (const float*)d_in[2];
    const float* pro_j = (const float*)d_in[3];
    float* out = (float*)d_out;

    tile_kernel<<<NTRI, 256>>>(emb_i, emb_j);
    reduce_kernel<<<33, 512>>>(emb_i, emb_j, pro_i, pro_j);
    combine_kernel<<<1, 32>>>(out);
}